// round 16
// baseline (speedup 1.0000x reference)
#include <cuda_runtime.h>
#include <math.h>

#define N_NODES 100000
#define E_EDGES 3200000
#define HID     1024
#define G_GRAPHS 64
#define CLASSES 40
#define CAP     128
#define BN_EPS  1e-5f

// ---------------- scratch (device globals; no allocation allowed) -----------
__device__ int    g_is64;
__device__ int    g_done;
__device__ int    g_cnt[N_NODES];
__device__ int    g_csr[N_NODES * CAP];
__device__ float4 g_y0[N_NODES];
__device__ float4 g_y1[N_NODES];
__device__ float4 g_xf[N_NODES];
__device__ float  g_acc[9];
__device__ float  g_Wa[3 * HID];
__device__ float  g_C[HID];
__device__ int    g_pool[G_GRAPHS * HID];
__device__ float  g_h1[G_GRAPHS * 512];
__device__ float  g_h2[G_GRAPHS * 256];

// ---------------- f32x2 helpers ---------------------------------------------
__device__ __forceinline__ unsigned long long pk2(float a, float b) {
    unsigned long long r;
    asm("mov.b64 %0, {%1, %2};" : "=l"(r) : "f"(a), "f"(b));
    return r;
}
__device__ __forceinline__ unsigned long long fma2(unsigned long long a,
                                                   unsigned long long b,
                                                   unsigned long long c) {
    unsigned long long d;
    asm("fma.rn.f32x2 %0, %1, %2, %3;" : "=l"(d) : "l"(a), "l"(b), "l"(c));
    return d;
}
__device__ __forceinline__ void upk2(unsigned long long p, float& lo, float& hi) {
    asm("mov.b64 {%0, %1}, %2;" : "=f"(lo), "=f"(hi) : "l"(p));
}

// ---------------- kernels ---------------------------------------------------

// zero scratch; thread 0 sniffs the index dtype (int64 ids < 2^31 -> hi=0)
__global__ void k_zero(const void* __restrict__ ei) {
    int i = blockIdx.x * blockDim.x + threadIdx.x;
    if (i == 0) {
        const unsigned long long* p = (const unsigned long long*)ei;
        int is64 = 1;
        #pragma unroll
        for (int k = 0; k < 16; k++)
            if (p[k] >> 32) { is64 = 0; break; }
        g_is64 = is64;
        g_done = 0;
    }
    if (i < N_NODES) g_cnt[i] = 0;
    if (i < G_GRAPHS * HID) g_pool[i] = 0;   // relu >= 0 -> exact identity
    if (i < 9) g_acc[i] = 0.f;
}

// build padded CSR + in-degree; 4 edges/thread, 16B vector loads
__global__ void k_build(const void* __restrict__ ei) {
    int t = blockIdx.x * blockDim.x + threadIdx.x;
    if (t * 4 >= E_EDGES) return;
    int r[4], c[4];
    if (g_is64) {
        const longlong2* pr = (const longlong2*)ei;
        const longlong2* pc = pr + (E_EDGES / 2);
        longlong2 r0 = pr[2 * t], r1 = pr[2 * t + 1];
        longlong2 c0 = pc[2 * t], c1 = pc[2 * t + 1];
        r[0] = (int)r0.x; r[1] = (int)r0.y; r[2] = (int)r1.x; r[3] = (int)r1.y;
        c[0] = (int)c0.x; c[1] = (int)c0.y; c[2] = (int)c1.x; c[3] = (int)c1.y;
    } else {
        const int4* pr = (const int4*)ei;
        const int4* pc = pr + (E_EDGES / 4);
        int4 ra = pr[t], ca = pc[t];
        r[0] = ra.x; r[1] = ra.y; r[2] = ra.z; r[3] = ra.w;
        c[0] = ca.x; c[1] = ca.y; c[2] = ca.z; c[3] = ca.w;
    }
    #pragma unroll
    for (int k = 0; k < 4; k++) {
        int p = atomicAdd(&g_cnt[c[k]], 1);
        if (p < CAP) g_csr[c[k] * CAP + p] = r[k];
    }
}

// y0 = rsqrt(deg) * pos   (deg = cnt + 1 with self loop)
__global__ void k_prep(const float* __restrict__ pos) {
    int i = blockIdx.x * blockDim.x + threadIdx.x;
    if (i >= N_NODES) return;
    float dis = rsqrtf((float)(g_cnt[i] + 1));
    g_y0[i] = make_float4(dis * pos[3 * i], dis * pos[3 * i + 1],
                          dis * pos[3 * i + 2], 0.f);
}

// y_{k+1}[i] = (y_k[i] + sum_nb y_k[src]) / deg_i  -- OCTET (8 lanes) per node;
// 8 contiguous 4B index reads = 1 sector per node-group (vs 2 for quads)
__global__ void k_prop(int flip) {
    const float4* __restrict__ src = flip ? g_y1 : g_y0;
    float4* __restrict__ dst       = flip ? g_y0 : g_y1;
    int t     = blockIdx.x * blockDim.x + threadIdx.x;
    int node  = t >> 3;
    int lane8 = t & 7;
    bool valid = (node < N_NODES);
    if (!valid) node = N_NODES - 1;
    int c  = g_cnt[node];
    int cc = min(c, CAP);
    const int* __restrict__ lst = g_csr + node * CAP;
    float sx = 0.f, sy = 0.f, sz = 0.f;
    #pragma unroll 4
    for (int i = lane8; i < cc; i += 8) {
        float4 v = src[__ldg(lst + i)];
        sx += v.x; sy += v.y; sz += v.z;
    }
    #pragma unroll
    for (int o = 4; o > 0; o >>= 1) {
        sx += __shfl_down_sync(0xffffffffu, sx, o);
        sy += __shfl_down_sync(0xffffffffu, sy, o);
        sz += __shfl_down_sync(0xffffffffu, sz, o);
    }
    if (valid && lane8 == 0) {
        float4 self = src[node];
        float w = 1.f / (float)(c + 1);
        dst[node] = make_float4(w * (sx + self.x), w * (sy + self.y),
                                w * (sz + self.z), 0.f);
    }
}

// FINAL propagation iteration fused with moment accumulation + BN0 fold:
// reads g_y0, writes g_xf = (sum+self)/sqrt(deg)  [ == y_final * sqrt(deg) ]
__global__ void k_prop_fin(const float* __restrict__ lin_w,
                           const float* __restrict__ lin_b,
                           const float* __restrict__ bn0_g,
                           const float* __restrict__ bn0_b) {
    const float4* __restrict__ src = g_y0;   // it4: flip=0
    int t     = blockIdx.x * blockDim.x + threadIdx.x;
    int node  = t >> 3;
    int lane8 = t & 7;
    bool valid = (node < N_NODES);
    if (!valid) node = N_NODES - 1;
    int c  = g_cnt[node];
    int cc = min(c, CAP);
    const int* __restrict__ lst = g_csr + node * CAP;
    float sx = 0.f, sy = 0.f, sz = 0.f;
    #pragma unroll 4
    for (int i = lane8; i < cc; i += 8) {
        float4 v = src[__ldg(lst + i)];
        sx += v.x; sy += v.y; sz += v.z;
    }
    #pragma unroll
    for (int o = 4; o > 0; o >>= 1) {
        sx += __shfl_down_sync(0xffffffffu, sx, o);
        sy += __shfl_down_sync(0xffffffffu, sy, o);
        sz += __shfl_down_sync(0xffffffffu, sz, o);
    }
    float v[9];
    #pragma unroll
    for (int k = 0; k < 9; k++) v[k] = 0.f;
    if (valid && lane8 == 0) {
        float4 self = src[node];
        float is = rsqrtf((float)(c + 1));
        float xx = (sx + self.x) * is;
        float xy = (sy + self.y) * is;
        float xz = (sz + self.z) * is;
        g_xf[node] = make_float4(xx, xy, xz, 0.f);
        v[0] = xx; v[1] = xy; v[2] = xz;
        v[3] = xx * xx; v[4] = xx * xy; v[5] = xx * xz;
        v[6] = xy * xy; v[7] = xy * xz; v[8] = xz * xz;
    }
    #pragma unroll
    for (int k = 0; k < 9; k++) {
        #pragma unroll
        for (int o = 16; o > 0; o >>= 1)
            v[k] += __shfl_down_sync(0xffffffffu, v[k], o);
    }
    if ((threadIdx.x & 31) == 0) {
        #pragma unroll
        for (int k = 0; k < 9; k++) atomicAdd(&g_acc[k], v[k]);
        __threadfence();
    }
    __shared__ int s_last;
    __syncthreads();
    if (threadIdx.x == 0) {
        int done = atomicAdd(&g_done, 1);
        s_last = (done == (int)gridDim.x - 1);
    }
    __syncthreads();
    if (!s_last) return;
    // ---- last block: fold BN0 into Wa/C (all other blocks' atomics done) ---
    __shared__ float sa[9];
    if (threadIdx.x < 9) sa[threadIdx.x] = __ldcg(&g_acc[threadIdx.x]);
    __syncthreads();
    const float invN = 1.f / (float)N_NODES;
    float m0 = sa[0] * invN, m1 = sa[1] * invN, m2 = sa[2] * invN;
    float c00 = sa[3] * invN - m0 * m0;
    float c01 = sa[4] * invN - m0 * m1;
    float c02 = sa[5] * invN - m0 * m2;
    float c11 = sa[6] * invN - m1 * m1;
    float c12 = sa[7] * invN - m1 * m2;
    float c22 = sa[8] * invN - m2 * m2;
    for (int j = threadIdx.x; j < HID; j += blockDim.x) {
        float w0 = lin_w[j], w1 = lin_w[HID + j], w2 = lin_w[2 * HID + j];
        float mean = m0 * w0 + m1 * w1 + m2 * w2 + lin_b[j];
        float var  = w0 * w0 * c00 + w1 * w1 * c11 + w2 * w2 * c22
                   + 2.f * (w0 * w1 * c01 + w0 * w2 * c02 + w1 * w2 * c12);
        float A = bn0_g[j] * rsqrtf(var + BN_EPS);
        g_Wa[j] = A * w0; g_Wa[HID + j] = A * w1; g_Wa[2 * HID + j] = A * w2;
        g_C[j] = bn0_b[j] + A * (lin_b[j] - mean);
    }
}

// fused Linear(3->1024)+BN+ReLU+segment_max; f32x2-packed, 2 nodes/iter
__global__ void __launch_bounds__(1024)
k_pool(const void* __restrict__ batch) {
    __shared__ __align__(8) float s_x[256], s_y[256], s_zc[256];
    __shared__ int s_b[256];
    __shared__ unsigned s_mask[4];
    int base  = blockIdx.x * 256;
    int count = min(256, N_NODES - base);
    int tid = threadIdx.x;
    if (tid < 256) {
        int t = min(tid, count - 1);   // pad by replication: max is idempotent
        float4 v = g_xf[base + t];
        s_x[tid] = v.x; s_y[tid] = v.y; s_zc[tid] = v.z;
        s_b[tid] = g_is64 ? (int)((const long long*)batch)[base + t]
                          : ((const int*)batch)[base + t];
    }
    __syncthreads();
    if (tid < 128) {   // per-pair "no boundary" bitmask (warps 0..3 full)
        int b0 = s_b[2 * tid], b1 = s_b[2 * tid + 1];
        int prev = (tid == 0) ? b0 : s_b[2 * tid - 1];
        bool clean = (b0 == b1) && (b0 == prev);
        unsigned bal = __ballot_sync(0xffffffffu, clean);
        if ((tid & 31) == 0) s_mask[tid >> 5] = bal;
    }
    __syncthreads();
    int j = tid;
    float w0 = g_Wa[j], w1 = g_Wa[HID + j], w2 = g_Wa[2 * HID + j], cj = g_C[j];
    unsigned long long w0p = pk2(w0, w0), w1p = pk2(w1, w1),
                       w2p = pk2(w2, w2), cjp = pk2(cj, cj);
    int gc = s_b[0];
    float m = 0.f;
    for (int w = 0; w < 4; w++) {
        unsigned mw = s_mask[w];
        #pragma unroll 8
        for (int ii = 0; ii < 32; ii++) {
            int i = w * 32 + ii;
            if ((mw >> ii) & 1u) {
                unsigned long long px = *(const unsigned long long*)(s_x  + 2 * i);
                unsigned long long py = *(const unsigned long long*)(s_y  + 2 * i);
                unsigned long long pz = *(const unsigned long long*)(s_zc + 2 * i);
                unsigned long long zp = fma2(w0p, px, fma2(w1p, py, fma2(w2p, pz, cjp)));
                float lo, hi; upk2(zp, lo, hi);
                m = fmaxf(m, lo); m = fmaxf(m, hi);
            } else {
                #pragma unroll
                for (int s = 0; s < 2; s++) {
                    int t = 2 * i + s;
                    int g = s_b[t];
                    if (g != gc) {
                        atomicMax(&g_pool[gc * HID + j], __float_as_int(m));
                        gc = g; m = 0.f;
                    }
                    float z = fmaf(w0, s_x[t], fmaf(w1, s_y[t], fmaf(w2, s_zc[t], cj)));
                    m = fmaxf(m, z);
                }
            }
        }
    }
    atomicMax(&g_pool[gc * HID + j], __float_as_int(m));
}

// tiled GEMM + training-mode BN(64 rows) + ReLU; block = 64 rows x 8 cols
__global__ void __launch_bounds__(512)
k_head(int layer, const float* __restrict__ W, const float* __restrict__ b,
       const float* __restrict__ gm, const float* __restrict__ bt) {
    const float* in; float* out; int Kin, Kout;
    if (layer == 1) { in = (const float*)g_pool; out = g_h1; Kin = 1024; Kout = 512; }
    else            { in = g_h1;                 out = g_h2; Kin = 512;  Kout = 256; }
    __shared__ float s_in[64 * 65];
    __shared__ float s_w[64 * 9];
    __shared__ float s_z[512];
    __shared__ float s_A[8], s_B[8];
    int tid = threadIdx.x;
    int r = tid >> 3, jj = tid & 7;
    int j = blockIdx.x * 8 + jj;
    float acc = 0.f;
    for (int k0 = 0; k0 < Kin; k0 += 64) {
        __syncthreads();
        #pragma unroll
        for (int s = 0; s < 8; s++) {
            int idx = s * 512 + tid;
            int row = idx >> 6, kk = idx & 63;
            s_in[row * 65 + kk] = in[row * Kin + k0 + kk];
        }
        s_w[(tid >> 3) * 9 + jj] = W[(k0 + (tid >> 3)) * Kout + j];
        __syncthreads();
        #pragma unroll
        for (int kk = 0; kk < 64; kk++)
            acc = fmaf(s_in[r * 65 + kk], s_w[kk * 9 + jj], acc);
    }
    float z = acc + b[j];
    s_z[tid] = z;
    __syncthreads();
    if (tid < 8) {
        float s = 0.f, q = 0.f;
        #pragma unroll
        for (int rr = 0; rr < 64; rr++) {
            float v = s_z[rr * 8 + tid];
            s += v; q = fmaf(v, v, q);
        }
        float mean = s * (1.f / 64.f);
        float var  = q * (1.f / 64.f) - mean * mean;
        float A = gm[blockIdx.x * 8 + tid] * rsqrtf(var + BN_EPS);
        s_A[tid] = A;
        s_B[tid] = bt[blockIdx.x * 8 + tid] - mean * A;
    }
    __syncthreads();
    out[r * Kout + j] = fmaxf(0.f, fmaf(z, s_A[jj], s_B[jj]));
}

// final Linear(256->40) + log_softmax; block per graph row
__global__ void k_out(const float* __restrict__ fc3_w,
                      const float* __restrict__ fc3_b,
                      float* __restrict__ out) {
    __shared__ float hr[256];
    __shared__ float zb[CLASSES];
    int row = blockIdx.x, tid = threadIdx.x;  // 64 threads
    for (int t = tid; t < 256; t += 64) hr[t] = g_h2[row * 256 + t];
    __syncthreads();
    if (tid < CLASSES) {
        float a = fc3_b[tid];
        for (int k = 0; k < 256; k++) a = fmaf(hr[k], fc3_w[k * CLASSES + tid], a);
        zb[tid] = a;
    }
    __syncthreads();
    if (tid < CLASSES) {
        float mx = -1e30f;
        for (int k = 0; k < CLASSES; k++) mx = fmaxf(mx, zb[k]);
        float sum = 0.f;
        for (int k = 0; k < CLASSES; k++) sum += expf(zb[k] - mx);
        out[row * CLASSES + tid] = zb[tid] - mx - logf(sum);
    }
}

// ---------------- launch -----------------------------------------------------

extern "C" void kernel_launch(void* const* d_in, const int* in_sizes, int n_in,
                              void* d_out, int out_size) {
    const float* pos   = (const float*)d_in[0];
    const void*  ei    = d_in[1];
    const void*  batch = d_in[2];
    const float* lin_w = (const float*)d_in[3];
    const float* lin_b = (const float*)d_in[4];
    const float* bn0_g = (const float*)d_in[5];
    const float* bn0_b = (const float*)d_in[6];
    const float* fc1_w = (const float*)d_in[7];
    const float* fc1_b = (const float*)d_in[8];
    const float* bn1_g = (const float*)d_in[9];
    const float* bn1_b = (const float*)d_in[10];
    const float* fc2_w = (const float*)d_in[11];
    const float* fc2_b = (const float*)d_in[12];
    const float* bn2_g = (const float*)d_in[13];
    const float* bn2_b = (const float*)d_in[14];
    const float* fc3_w = (const float*)d_in[15];
    const float* fc3_b = (const float*)d_in[16];
    float* out = (float*)d_out;

    k_zero<<<(N_NODES + 255) / 256, 256>>>(ei);
    k_build<<<(E_EDGES / 4 + 255) / 256, 256>>>(ei);
    k_prep<<<(N_NODES + 255) / 256, 256>>>(pos);
    for (int it = 0; it < 4; it++)                         // iterations 0..3
        k_prop<<<(N_NODES * 8 + 255) / 256, 256>>>(it & 1);
    k_prop_fin<<<(N_NODES * 8 + 255) / 256, 256>>>(        // iteration 4 + BN0
        lin_w, lin_b, bn0_g, bn0_b);
    k_pool<<<(N_NODES + 255) / 256, 1024>>>(batch);
    k_head<<<64, 512>>>(1, fc1_w, fc1_b, bn1_g, bn1_b);
    k_head<<<32, 512>>>(2, fc2_w, fc2_b, bn2_g, bn2_b);
    k_out<<<G_GRAPHS, 64>>>(fc3_w, fc3_b, out);
}

// round 17
// speedup vs baseline: 2.4158x; 2.4158x over previous
#include <cuda_runtime.h>
#include <math.h>

#define N_NODES 100000
#define E_EDGES 3200000
#define HID     1024
#define G_GRAPHS 64
#define CLASSES 40
#define CAP     128
#define BN_EPS  1e-5f

// ---------------- scratch (device globals; no allocation allowed) -----------
__device__ int    g_is64;
__device__ int    g_done;
__device__ int    g_cnt[N_NODES];
__device__ int    g_csr[N_NODES * CAP];
__device__ float4 g_y0[N_NODES];
__device__ float4 g_y1[N_NODES];
__device__ float4 g_xf[N_NODES];
__device__ float  g_acc[9];
__device__ float  g_Wa[3 * HID];
__device__ float  g_C[HID];
__device__ int    g_pool[G_GRAPHS * HID];
__device__ float  g_h1[G_GRAPHS * 512];
__device__ float  g_h2[G_GRAPHS * 256];

// ---------------- f32x2 helpers ---------------------------------------------
__device__ __forceinline__ unsigned long long pk2(float a, float b) {
    unsigned long long r;
    asm("mov.b64 %0, {%1, %2};" : "=l"(r) : "f"(a), "f"(b));
    return r;
}
__device__ __forceinline__ unsigned long long fma2(unsigned long long a,
                                                   unsigned long long b,
                                                   unsigned long long c) {
    unsigned long long d;
    asm("fma.rn.f32x2 %0, %1, %2, %3;" : "=l"(d) : "l"(a), "l"(b), "l"(c));
    return d;
}
__device__ __forceinline__ void upk2(unsigned long long p, float& lo, float& hi) {
    asm("mov.b64 {%0, %1}, %2;" : "=f"(lo), "=f"(hi) : "l"(p));
}

// ---------------- kernels ---------------------------------------------------

// zero scratch; thread 0 sniffs the index dtype (int64 ids < 2^31 -> hi=0)
__global__ void k_zero(const void* __restrict__ ei) {
    int i = blockIdx.x * blockDim.x + threadIdx.x;
    if (i == 0) {
        const unsigned long long* p = (const unsigned long long*)ei;
        int is64 = 1;
        #pragma unroll
        for (int k = 0; k < 16; k++)
            if (p[k] >> 32) { is64 = 0; break; }
        g_is64 = is64;
        g_done = 0;
    }
    if (i < N_NODES) g_cnt[i] = 0;
    if (i < G_GRAPHS * HID) g_pool[i] = 0;   // relu >= 0 -> exact identity
    if (i < 9) g_acc[i] = 0.f;
}

// build padded CSR + in-degree; 4 edges/thread, 16B vector loads
__global__ void k_build(const void* __restrict__ ei) {
    int t = blockIdx.x * blockDim.x + threadIdx.x;
    if (t * 4 >= E_EDGES) return;
    int r[4], c[4];
    if (g_is64) {
        const longlong2* pr = (const longlong2*)ei;
        const longlong2* pc = pr + (E_EDGES / 2);
        longlong2 r0 = pr[2 * t], r1 = pr[2 * t + 1];
        longlong2 c0 = pc[2 * t], c1 = pc[2 * t + 1];
        r[0] = (int)r0.x; r[1] = (int)r0.y; r[2] = (int)r1.x; r[3] = (int)r1.y;
        c[0] = (int)c0.x; c[1] = (int)c0.y; c[2] = (int)c1.x; c[3] = (int)c1.y;
    } else {
        const int4* pr = (const int4*)ei;
        const int4* pc = pr + (E_EDGES / 4);
        int4 ra = pr[t], ca = pc[t];
        r[0] = ra.x; r[1] = ra.y; r[2] = ra.z; r[3] = ra.w;
        c[0] = ca.x; c[1] = ca.y; c[2] = ca.z; c[3] = ca.w;
    }
    #pragma unroll
    for (int k = 0; k < 4; k++) {
        int p = atomicAdd(&g_cnt[c[k]], 1);
        if (p < CAP) g_csr[c[k] * CAP + p] = r[k];
    }
}

// y0 = rsqrt(deg) * pos   (deg = cnt + 1 with self loop)
__global__ void k_prep(const float* __restrict__ pos) {
    int i = blockIdx.x * blockDim.x + threadIdx.x;
    if (i >= N_NODES) return;
    float dis = rsqrtf((float)(g_cnt[i] + 1));
    g_y0[i] = make_float4(dis * pos[3 * i], dis * pos[3 * i + 1],
                          dis * pos[3 * i + 2], 0.f);
}

// y_{k+1}[i] = (y_k[i] + sum_nb y_k[src]) / deg_i  -- OCTET (8 lanes) per node;
// 8 contiguous 4B index reads = 1 sector per node-group (validated 20.0us/iter)
__global__ void k_prop(int flip) {
    const float4* __restrict__ src = flip ? g_y1 : g_y0;
    float4* __restrict__ dst       = flip ? g_y0 : g_y1;
    int t     = blockIdx.x * blockDim.x + threadIdx.x;
    int node  = t >> 3;
    int lane8 = t & 7;
    bool valid = (node < N_NODES);
    if (!valid) node = N_NODES - 1;
    int c  = g_cnt[node];
    int cc = min(c, CAP);
    const int* __restrict__ lst = g_csr + node * CAP;
    float sx = 0.f, sy = 0.f, sz = 0.f;
    #pragma unroll 4
    for (int i = lane8; i < cc; i += 8) {
        float4 v = src[__ldg(lst + i)];
        sx += v.x; sy += v.y; sz += v.z;
    }
    #pragma unroll
    for (int o = 4; o > 0; o >>= 1) {
        sx += __shfl_down_sync(0xffffffffu, sx, o);
        sy += __shfl_down_sync(0xffffffffu, sy, o);
        sz += __shfl_down_sync(0xffffffffu, sz, o);
    }
    if (valid && lane8 == 0) {
        float4 self = src[node];
        float w = 1.f / (float)(c + 1);
        dst[node] = make_float4(w * (sx + self.x), w * (sy + self.y),
                                w * (sz + self.z), 0.f);
    }
}

// xf = y * sqrt(deg); block-reduced moments (ONE atomic set per block);
// LAST block folds BN0 into Wa/C
__global__ void k_finmom(const float* __restrict__ lin_w,
                         const float* __restrict__ lin_b,
                         const float* __restrict__ bn0_g,
                         const float* __restrict__ bn0_b) {
    int i = blockIdx.x * blockDim.x + threadIdx.x;
    float v[9];
    #pragma unroll
    for (int k = 0; k < 9; k++) v[k] = 0.f;
    if (i < N_NODES) {
        float s = sqrtf((float)(g_cnt[i] + 1));
        float4 t = g_y1[i];
        float4 xf = make_float4(t.x * s, t.y * s, t.z * s, 0.f);
        g_xf[i] = xf;
        v[0] = xf.x; v[1] = xf.y; v[2] = xf.z;
        v[3] = xf.x * xf.x; v[4] = xf.x * xf.y; v[5] = xf.x * xf.z;
        v[6] = xf.y * xf.y; v[7] = xf.y * xf.z; v[8] = xf.z * xf.z;
    }
    #pragma unroll
    for (int k = 0; k < 9; k++) {
        #pragma unroll
        for (int o = 16; o > 0; o >>= 1)
            v[k] += __shfl_down_sync(0xffffffffu, v[k], o);
    }
    __shared__ float s_red[8][9];               // 8 warps per 256-thread block
    int wrp = threadIdx.x >> 5;
    if ((threadIdx.x & 31) == 0) {
        #pragma unroll
        for (int k = 0; k < 9; k++) s_red[wrp][k] = v[k];
    }
    __syncthreads();
    if (threadIdx.x == 0) {                     // one atomic set per BLOCK
        #pragma unroll
        for (int k = 0; k < 9; k++) {
            float a = s_red[0][k];
            #pragma unroll
            for (int w = 1; w < 8; w++) a += s_red[w][k];
            atomicAdd(&g_acc[k], a);
        }
        __threadfence();
    }
    __shared__ int s_last;
    __syncthreads();
    if (threadIdx.x == 0) {
        int done = atomicAdd(&g_done, 1);
        s_last = (done == (int)gridDim.x - 1);
    }
    __syncthreads();
    if (!s_last) return;
    // ---- last block: fold BN0 (runs once, all other blocks' atomics done) --
    __shared__ float sa[9];
    if (threadIdx.x < 9) sa[threadIdx.x] = __ldcg(&g_acc[threadIdx.x]);
    __syncthreads();
    const float invN = 1.f / (float)N_NODES;
    float m0 = sa[0] * invN, m1 = sa[1] * invN, m2 = sa[2] * invN;
    float c00 = sa[3] * invN - m0 * m0;
    float c01 = sa[4] * invN - m0 * m1;
    float c02 = sa[5] * invN - m0 * m2;
    float c11 = sa[6] * invN - m1 * m1;
    float c12 = sa[7] * invN - m1 * m2;
    float c22 = sa[8] * invN - m2 * m2;
    for (int it = 0; it < HID / 256; it++) {
        int j = it * 256 + threadIdx.x;
        float w0 = lin_w[j], w1 = lin_w[HID + j], w2 = lin_w[2 * HID + j];
        float mean = m0 * w0 + m1 * w1 + m2 * w2 + lin_b[j];
        float var  = w0 * w0 * c00 + w1 * w1 * c11 + w2 * w2 * c22
                   + 2.f * (w0 * w1 * c01 + w0 * w2 * c02 + w1 * w2 * c12);
        float A = bn0_g[j] * rsqrtf(var + BN_EPS);
        g_Wa[j] = A * w0; g_Wa[HID + j] = A * w1; g_Wa[2 * HID + j] = A * w2;
        g_C[j] = bn0_b[j] + A * (lin_b[j] - mean);
    }
}

// fused Linear(3->1024)+BN+ReLU+segment_max; f32x2-packed, 2 nodes/iter
__global__ void __launch_bounds__(1024)
k_pool(const void* __restrict__ batch) {
    __shared__ __align__(8) float s_x[256], s_y[256], s_zc[256];
    __shared__ int s_b[256];
    __shared__ unsigned s_mask[4];
    int base  = blockIdx.x * 256;
    int count = min(256, N_NODES - base);
    int tid = threadIdx.x;
    if (tid < 256) {
        int t = min(tid, count - 1);   // pad by replication: max is idempotent
        float4 v = g_xf[base + t];
        s_x[tid] = v.x; s_y[tid] = v.y; s_zc[tid] = v.z;
        s_b[tid] = g_is64 ? (int)((const long long*)batch)[base + t]
                          : ((const int*)batch)[base + t];
    }
    __syncthreads();
    if (tid < 128) {   // per-pair "no boundary" bitmask (warps 0..3 full)
        int b0 = s_b[2 * tid], b1 = s_b[2 * tid + 1];
        int prev = (tid == 0) ? b0 : s_b[2 * tid - 1];
        bool clean = (b0 == b1) && (b0 == prev);
        unsigned bal = __ballot_sync(0xffffffffu, clean);
        if ((tid & 31) == 0) s_mask[tid >> 5] = bal;
    }
    __syncthreads();
    int j = tid;
    float w0 = g_Wa[j], w1 = g_Wa[HID + j], w2 = g_Wa[2 * HID + j], cj = g_C[j];
    unsigned long long w0p = pk2(w0, w0), w1p = pk2(w1, w1),
                       w2p = pk2(w2, w2), cjp = pk2(cj, cj);
    int gc = s_b[0];
    float m = 0.f;
    for (int w = 0; w < 4; w++) {
        unsigned mw = s_mask[w];
        #pragma unroll 8
        for (int ii = 0; ii < 32; ii++) {
            int i = w * 32 + ii;
            if ((mw >> ii) & 1u) {
                unsigned long long px = *(const unsigned long long*)(s_x  + 2 * i);
                unsigned long long py = *(const unsigned long long*)(s_y  + 2 * i);
                unsigned long long pz = *(const unsigned long long*)(s_zc + 2 * i);
                unsigned long long zp = fma2(w0p, px, fma2(w1p, py, fma2(w2p, pz, cjp)));
                float lo, hi; upk2(zp, lo, hi);
                m = fmaxf(m, lo); m = fmaxf(m, hi);
            } else {
                #pragma unroll
                for (int s = 0; s < 2; s++) {
                    int t = 2 * i + s;
                    int g = s_b[t];
                    if (g != gc) {
                        atomicMax(&g_pool[gc * HID + j], __float_as_int(m));
                        gc = g; m = 0.f;
                    }
                    float z = fmaf(w0, s_x[t], fmaf(w1, s_y[t], fmaf(w2, s_zc[t], cj)));
                    m = fmaxf(m, z);
                }
            }
        }
    }
    atomicMax(&g_pool[gc * HID + j], __float_as_int(m));
}

// tiled GEMM + training-mode BN(64 rows) + ReLU; block = 64 rows x 8 cols
__global__ void __launch_bounds__(512)
k_head(int layer, const float* __restrict__ W, const float* __restrict__ b,
       const float* __restrict__ gm, const float* __restrict__ bt) {
    const float* in; float* out; int Kin, Kout;
    if (layer == 1) { in = (const float*)g_pool; out = g_h1; Kin = 1024; Kout = 512; }
    else            { in = g_h1;                 out = g_h2; Kin = 512;  Kout = 256; }
    __shared__ float s_in[64 * 65];
    __shared__ float s_w[64 * 9];
    __shared__ float s_z[512];
    __shared__ float s_A[8], s_B[8];
    int tid = threadIdx.x;
    int r = tid >> 3, jj = tid & 7;
    int j = blockIdx.x * 8 + jj;
    float acc = 0.f;
    for (int k0 = 0; k0 < Kin; k0 += 64) {
        __syncthreads();
        #pragma unroll
        for (int s = 0; s < 8; s++) {
            int idx = s * 512 + tid;
            int row = idx >> 6, kk = idx & 63;
            s_in[row * 65 + kk] = in[row * Kin + k0 + kk];
        }
        s_w[(tid >> 3) * 9 + jj] = W[(k0 + (tid >> 3)) * Kout + j];
        __syncthreads();
        #pragma unroll
        for (int kk = 0; kk < 64; kk++)
            acc = fmaf(s_in[r * 65 + kk], s_w[kk * 9 + jj], acc);
    }
    float z = acc + b[j];
    s_z[tid] = z;
    __syncthreads();
    if (tid < 8) {
        float s = 0.f, q = 0.f;
        #pragma unroll
        for (int rr = 0; rr < 64; rr++) {
            float v = s_z[rr * 8 + tid];
            s += v; q = fmaf(v, v, q);
        }
        float mean = s * (1.f / 64.f);
        float var  = q * (1.f / 64.f) - mean * mean;
        float A = gm[blockIdx.x * 8 + tid] * rsqrtf(var + BN_EPS);
        s_A[tid] = A;
        s_B[tid] = bt[blockIdx.x * 8 + tid] - mean * A;
    }
    __syncthreads();
    out[r * Kout + j] = fmaxf(0.f, fmaf(z, s_A[jj], s_B[jj]));
}

// final Linear(256->40) + log_softmax; block per graph row
__global__ void k_out(const float* __restrict__ fc3_w,
                      const float* __restrict__ fc3_b,
                      float* __restrict__ out) {
    __shared__ float hr[256];
    __shared__ float zb[CLASSES];
    int row = blockIdx.x, tid = threadIdx.x;  // 64 threads
    for (int t = tid; t < 256; t += 64) hr[t] = g_h2[row * 256 + t];
    __syncthreads();
    if (tid < CLASSES) {
        float a = fc3_b[tid];
        for (int k = 0; k < 256; k++) a = fmaf(hr[k], fc3_w[k * CLASSES + tid], a);
        zb[tid] = a;
    }
    __syncthreads();
    if (tid < CLASSES) {
        float mx = -1e30f;
        for (int k = 0; k < CLASSES; k++) mx = fmaxf(mx, zb[k]);
        float sum = 0.f;
        for (int k = 0; k < CLASSES; k++) sum += expf(zb[k] - mx);
        out[row * CLASSES + tid] = zb[tid] - mx - logf(sum);
    }
}

// ---------------- launch -----------------------------------------------------

extern "C" void kernel_launch(void* const* d_in, const int* in_sizes, int n_in,
                              void* d_out, int out_size) {
    const float* pos   = (const float*)d_in[0];
    const void*  ei    = d_in[1];
    const void*  batch = d_in[2];
    const float* lin_w = (const float*)d_in[3];
    const float* lin_b = (const float*)d_in[4];
    const float* bn0_g = (const float*)d_in[5];
    const float* bn0_b = (const float*)d_in[6];
    const float* fc1_w = (const float*)d_in[7];
    const float* fc1_b = (const float*)d_in[8];
    const float* bn1_g = (const float*)d_in[9];
    const float* bn1_b = (const float*)d_in[10];
    const float* fc2_w = (const float*)d_in[11];
    const float* fc2_b = (const float*)d_in[12];
    const float* bn2_g = (const float*)d_in[13];
    const float* bn2_b = (const float*)d_in[14];
    const float* fc3_w = (const float*)d_in[15];
    const float* fc3_b = (const float*)d_in[16];
    float* out = (float*)d_out;

    k_zero<<<(N_NODES + 255) / 256, 256>>>(ei);
    k_build<<<(E_EDGES / 4 + 255) / 256, 256>>>(ei);
    k_prep<<<(N_NODES + 255) / 256, 256>>>(pos);
    for (int it = 0; it < 5; it++)
        k_prop<<<(N_NODES * 8 + 255) / 256, 256>>>(it & 1);
    k_finmom<<<(N_NODES + 255) / 256, 256>>>(lin_w, lin_b, bn0_g, bn0_b);
    k_pool<<<(N_NODES + 255) / 256, 1024>>>(batch);
    k_head<<<64, 512>>>(1, fc1_w, fc1_b, bn1_g, bn1_b);
    k_head<<<32, 512>>>(2, fc2_w, fc2_b, bn2_g, bn2_b);
    k_out<<<G_GRAPHS, 64>>>(fc3_w, fc3_b, out);
}